// round 5
// baseline (speedup 1.0000x reference)
#include <cuda_runtime.h>
#include <cuda_fp16.h>
#include <cstdint>

#define D_FEAT      64
#define N_NODES_MAX 100000
#define EPS         128           // edges per 16-thread group
#define SUBS        8             // groups per block
#define EPB         (EPS * SUBS)  // 1024 edges per block
#define THREADS     128
#define MAX_GROUPS  20480

// Scratch (allocation-free per harness rules). tmp is fp16.
__device__ __half g_tmp[(size_t)N_NODES_MAX * D_FEAT];
__device__ float  g_carry[(size_t)MAX_GROUPS * D_FEAT];
__device__ int    g_carry_row[MAX_GROUPS];

__device__ __forceinline__ void red_add_v4(float* p, float4 a) {
    asm volatile("red.global.add.v4.f32 [%0], {%1, %2, %3, %4};"
                 :: "l"(p), "f"(a.x), "f"(a.y), "f"(a.z), "f"(a.w)
                 : "memory");
}
__device__ __forceinline__ void red_add_h2(uint32_t* p, __half2 v) {
    asm volatile("red.global.add.noftz.f16x2 [%0], %1;"
                 :: "l"(p), "r"(*reinterpret_cast<uint32_t*>(&v))
                 : "memory");
}

// ---- per-dtype row load/store helpers (d4-thread owns 4 features) ----
template <bool HALF>
__device__ __forceinline__ float4 ld_feat(const char* p) {
    if (HALF) {
        uint2 r = *reinterpret_cast<const uint2*>(p);
        float2 a = __half22float2(*reinterpret_cast<__half2*>(&r.x));
        float2 b = __half22float2(*reinterpret_cast<__half2*>(&r.y));
        return make_float4(a.x, a.y, b.x, b.y);
    } else {
        return *reinterpret_cast<const float4*>(p);
    }
}
template <bool HALF>
__device__ __forceinline__ void st_feat(char* p, float4 v) {
    if (HALF) {
        uint2 u;
        __half2 h0 = __float22half2_rn(make_float2(v.x, v.y));
        __half2 h1 = __float22half2_rn(make_float2(v.z, v.w));
        u.x = *reinterpret_cast<uint32_t*>(&h0);
        u.y = *reinterpret_cast<uint32_t*>(&h1);
        *reinterpret_cast<uint2*>(p) = u;
    } else {
        *reinterpret_cast<float4*>(p) = v;
    }
}

// Sorted-row SpMM, carry-based segmented reduction (no pre-zeroed dst).
template <bool SRC_H, bool DST_H>
__global__ void __launch_bounds__(THREADS)
spmm_kernel(const char* __restrict__ src,
            const int*  __restrict__ erow,
            const int*  __restrict__ ecol,
            const float* __restrict__ eval,
            char*       __restrict__ dst,
            float*      __restrict__ carry,
            int*        __restrict__ carry_row,
            int n_edges, int n_rows) {
    constexpr int SRC_RB  = SRC_H ? 128 : 256;   // bytes per feature row
    constexpr int DST_RB  = DST_H ? 128 : 256;
    constexpr int SRC_TB  = SRC_H ? 8 : 16;      // bytes per thread per row
    constexpr int DST_TB  = DST_H ? 8 : 16;

    __shared__ alignas(16) int   s_row[EPB];
    __shared__ alignas(16) int   s_off[EPB];     // col * SRC_RB
    __shared__ alignas(16) float s_val[EPB];

    const int base = blockIdx.x * EPB;
    const int tid  = threadIdx.x;

    // Vectorized staging; pad with last valid row, val = 0.
    #pragma unroll
    for (int i = tid * 4; i < EPB; i += THREADS * 4) {
        const int e = base + i;
        if (e + 3 < n_edges) {
            int4   r = *reinterpret_cast<const int4*>(erow + e);
            int4   c = *reinterpret_cast<const int4*>(ecol + e);
            float4 v = *reinterpret_cast<const float4*>(eval + e);
            c.x *= SRC_RB; c.y *= SRC_RB; c.z *= SRC_RB; c.w *= SRC_RB;
            *reinterpret_cast<int4*>(s_row + i)   = r;
            *reinterpret_cast<int4*>(s_off + i)   = c;
            *reinterpret_cast<float4*>(s_val + i) = v;
        } else {
            #pragma unroll
            for (int k = 0; k < 4; k++) {
                int ee   = e + k;
                int esrc = min(ee, n_edges - 1);
                int in   = (ee < n_edges);
                s_row[i + k] = erow[esrc];
                s_off[i + k] = in ? ecol[esrc] * SRC_RB : 0;
                s_val[i + k] = in ? eval[esrc] : 0.f;
            }
        }
    }
    __syncthreads();

    const int d4   = tid & 15;
    const int sub  = tid >> 4;
    const int off  = sub * EPS;
    const int gid  = blockIdx.x * SUBS + sub;
    const int goff = base + off;
    const char* sp = src + d4 * SRC_TB;
    char*       dp = dst + d4 * DST_TB;
    const float4 z4 = make_float4(0.f, 0.f, 0.f, 0.f);

    if (goff >= n_edges) {
        if (d4 == 0) carry_row[gid] = -1;
        return;
    }

    const int first = s_row[off];
    const int prev  = (off > 0) ? s_row[off - 1]
                                : ((goff == 0) ? -1 : erow[goff - 1]);
    const bool continuation = (prev == first);
    if (d4 == 0) carry_row[gid] = continuation ? first : -1;

    // Leading gap rows (prev, first): no edges anywhere -> zeros.
    for (int rr = prev + 1; rr < first; rr++)
        st_feat<DST_H>(dp + (size_t)rr * DST_RB, z4);

    int    cur       = first;
    bool   first_run = true;
    float4 acc       = make_float4(0.f, 0.f, 0.f, 0.f);

    for (int ib = 0; ib < EPS; ib += 8) {
        const int4   ra = *reinterpret_cast<const int4*>(s_row + off + ib);
        const int4   rb = *reinterpret_cast<const int4*>(s_row + off + ib + 4);
        const int4   ca = *reinterpret_cast<const int4*>(s_off + off + ib);
        const int4   cb = *reinterpret_cast<const int4*>(s_off + off + ib + 4);
        const float4 va = *reinterpret_cast<const float4*>(s_val + off + ib);
        const float4 vb = *reinterpret_cast<const float4*>(s_val + off + ib + 4);

        // 8 gathers in flight (MLP = 8)
        const float4 g0 = ld_feat<SRC_H>(sp + ca.x);
        const float4 g1 = ld_feat<SRC_H>(sp + ca.y);
        const float4 g2 = ld_feat<SRC_H>(sp + ca.z);
        const float4 g3 = ld_feat<SRC_H>(sp + ca.w);
        const float4 g4 = ld_feat<SRC_H>(sp + cb.x);
        const float4 g5 = ld_feat<SRC_H>(sp + cb.y);
        const float4 g6 = ld_feat<SRC_H>(sp + cb.z);
        const float4 g7 = ld_feat<SRC_H>(sp + cb.w);

        #define STEP(R, V, G)                                                \
        do {                                                                 \
            if ((R) != cur) {                                                \
                if (first_run && continuation) {                             \
                    *reinterpret_cast<float4*>(                              \
                        carry + (size_t)gid * D_FEAT + d4 * 4) = acc;        \
                } else {                                                     \
                    st_feat<DST_H>(dp + (size_t)cur * DST_RB, acc);          \
                }                                                            \
                first_run = false;                                           \
                for (int rr = cur + 1; rr < (R); rr++)                       \
                    st_feat<DST_H>(dp + (size_t)rr * DST_RB, z4);            \
                acc = make_float4(0.f, 0.f, 0.f, 0.f);                       \
                cur = (R);                                                   \
            }                                                                \
            acc.x += (V) * (G).x;                                            \
            acc.y += (V) * (G).y;                                            \
            acc.z += (V) * (G).z;                                            \
            acc.w += (V) * (G).w;                                            \
        } while (0)

        STEP(ra.x, va.x, g0);
        STEP(ra.y, va.y, g1);
        STEP(ra.z, va.z, g2);
        STEP(ra.w, va.w, g3);
        STEP(rb.x, vb.x, g4);
        STEP(rb.y, vb.y, g5);
        STEP(rb.z, vb.z, g6);
        STEP(rb.w, vb.w, g7);
        #undef STEP
    }

    // Final flush.
    if (first_run && continuation) {
        *reinterpret_cast<float4*>(carry + (size_t)gid * D_FEAT + d4 * 4) = acc;
    } else {
        st_feat<DST_H>(dp + (size_t)cur * DST_RB, acc);
    }

    // Group containing the global last edge zeroes trailing rows.
    if (goff <= n_edges - 1 && n_edges - 1 < goff + EPS) {
        for (int rr = cur + 1; rr < n_rows; rr++)
            st_feat<DST_H>(dp + (size_t)rr * DST_RB, z4);
    }
}

// Add per-group leading-run carries into the STG'd base values.
template <bool DST_H>
__global__ void fixup_kernel(char* __restrict__ dst,
                             const float* __restrict__ carry,
                             const int*   __restrict__ carry_row,
                             int n_groups) {
    int t  = blockIdx.x * blockDim.x + threadIdx.x;
    int g  = t >> 4;
    int d4 = t & 15;
    if (g >= n_groups) return;
    int r = carry_row[g];
    if (r < 0) return;
    float4 c = *reinterpret_cast<const float4*>(carry + (size_t)g * D_FEAT + d4 * 4);
    if (DST_H) {
        uint32_t* p = reinterpret_cast<uint32_t*>(dst + (size_t)r * 128 + d4 * 8);
        red_add_h2(p + 0, __float22half2_rn(make_float2(c.x, c.y)));
        red_add_h2(p + 1, __float22half2_rn(make_float2(c.z, c.w)));
    } else {
        red_add_v4(reinterpret_cast<float*>(dst + (size_t)r * 256 + d4 * 16), c);
    }
}

extern "C" void kernel_launch(void* const* d_in, const int* in_sizes, int n_in,
                              void* d_out, int out_size) {
    const char*  x    = (const char*) d_in[0];
    const int*   erow = (const int*)  d_in[1];
    const int*   ecol = (const int*)  d_in[2];
    const float* eval = (const float*)d_in[3];
    char*        out  = (char*)d_out;

    const int n_edges = in_sizes[1];
    const int n_rows  = out_size / D_FEAT;

    void *tmp_sym = nullptr, *cv_sym = nullptr, *cr_sym = nullptr;
    cudaGetSymbolAddress(&tmp_sym, g_tmp);
    cudaGetSymbolAddress(&cv_sym,  g_carry);
    cudaGetSymbolAddress(&cr_sym,  g_carry_row);
    char*  tmp  = (char*)tmp_sym;
    float* cval = (float*)cv_sym;
    int*   crow = (int*)cr_sym;

    const int sgrid    = (n_edges + EPB - 1) / EPB;
    const int n_groups = sgrid * SUBS;
    const int fgrid    = (n_groups * 16 + THREADS - 1) / THREADS;

    // Hop 1: tmp(fp16) = A @ x(fp32)
    spmm_kernel<false, true><<<sgrid, THREADS>>>(x, erow, ecol, eval, tmp,
                                                 cval, crow, n_edges, n_rows);
    fixup_kernel<true><<<fgrid, THREADS>>>(tmp, cval, crow, n_groups);

    // Hop 2: out(fp32) = A @ tmp(fp16)
    spmm_kernel<true, false><<<sgrid, THREADS>>>(tmp, erow, ecol, eval, out,
                                                 cval, crow, n_edges, n_rows);
    fixup_kernel<false><<<fgrid, THREADS>>>(out, cval, crow, n_groups);
}